// round 6
// baseline (speedup 1.0000x reference)
#include <cuda_runtime.h>
#include <cuda.h>
#include <cstdint>

#define TOKENS 8192
#define IN_F   4096
#define OUT_F  4096

#if defined(__CUDA_ARCH_FEAT_SM103_ALL) || defined(__CUDA_ARCH_FEAT_SM100_ALL) || defined(__CUDA_ARCH_FEAT_SM101_ALL)
#define HAS_TC 1
#else
#define HAS_TC 0
#endif

#define CLUSTER_Y 4

// ---------------- scratch (device globals: no allocations allowed) ----------
__device__ float g_xh[(size_t)TOKENS * IN_F];   // Hadamard-transformed x (tf32-rounded)
__device__ float g_w [(size_t)OUT_F  * IN_F];   // dequantized W (tf32-rounded)

// ---------------- small PTX helpers ----------------------------------------
__device__ __forceinline__ uint32_t smem_u32(const void* p) {
    uint32_t a;
    asm("{ .reg .u64 t; cvta.to.shared.u64 t, %1; cvt.u32.u64 %0, t; }" : "=r"(a) : "l"(p));
    return a;
}
__device__ __forceinline__ float tf32r(float x) {
    uint32_t u; asm("cvt.rna.tf32.f32 %0, %1;" : "=r"(u) : "f"(x));
    return __uint_as_float(u);
}
__device__ __forceinline__ void mbar_init(uint32_t a, uint32_t cnt) {
    asm volatile("mbarrier.init.shared.b64 [%0], %1;" :: "r"(a), "r"(cnt) : "memory");
}
__device__ __forceinline__ void mbar_expect(uint32_t a, uint32_t bytes) {
    asm volatile("mbarrier.arrive.expect_tx.shared.b64 _, [%0], %1;" :: "r"(a), "r"(bytes) : "memory");
}
__device__ __forceinline__ void mbar_wait(uint32_t a, uint32_t parity) {
    asm volatile(
        "{\n\t.reg .pred P;\n\t"
        "WAITLP_%=:\n\t"
        "mbarrier.try_wait.parity.shared::cta.b64 P, [%0], %1, 0x989680;\n\t"
        "@!P bra WAITLP_%=;\n\t"
        "}" :: "r"(a), "r"(parity) : "memory");
}
__device__ __forceinline__ void tma2d(uint32_t dst, const void* map, int cx, int cy, uint32_t bar) {
    asm volatile(
        "cp.async.bulk.tensor.2d.shared::cta.global.tile.mbarrier::complete_tx::bytes "
        "[%0], [%1, {%2, %3}], [%4];"
        :: "r"(dst), "l"(map), "r"(cx), "r"(cy), "r"(bar) : "memory");
}
__device__ __forceinline__ uint32_t sw128(uint32_t o) {   // Swizzle<3,4,3>
    return o ^ ((o >> 3) & 0x70);
}
__device__ __forceinline__ float lds32(uint32_t a) {
    uint32_t v; asm volatile("ld.shared.b32 %0, [%1];" : "=r"(v) : "r"(a));
    return __uint_as_float(v);
}
__device__ __forceinline__ uint32_t ctarank() {
    uint32_t r; asm("mov.u32 %0, %%cluster_ctarank;" : "=r"(r)); return r;
}

// ---------------- kernel 1: blockwise FWHT of x (block = 1024) --------------
// Bit coverage (index = 10 bits):
//   phase 1: r8 over j in layout idx = t + 128*j  -> bits {7,8,9}
//   phase 2: r8 over q in layout idx = 8*t + q    -> bits {0,1,2}
//            shfl.bfly m=1,2,4,8 over lane        -> bits {3,4,5,6}
__device__ __forceinline__ void r8(float v[8]) {
    float a;
    a = v[0]; v[0] = a + v[1]; v[1] = a - v[1];
    a = v[2]; v[2] = a + v[3]; v[3] = a - v[3];
    a = v[4]; v[4] = a + v[5]; v[5] = a - v[5];
    a = v[6]; v[6] = a + v[7]; v[7] = a - v[7];
    a = v[0]; v[0] = a + v[2]; v[2] = a - v[2];
    a = v[1]; v[1] = a + v[3]; v[3] = a - v[3];
    a = v[4]; v[4] = a + v[6]; v[6] = a - v[6];
    a = v[5]; v[5] = a + v[7]; v[7] = a - v[7];
    a = v[0]; v[0] = a + v[4]; v[4] = a - v[4];
    a = v[1]; v[1] = a + v[5]; v[5] = a - v[5];
    a = v[2]; v[2] = a + v[6]; v[6] = a - v[6];
    a = v[3]; v[3] = a + v[7]; v[7] = a - v[7];
}

__global__ void __launch_bounds__(128) fwht_kernel(const float* __restrict__ x,
                                                   float* __restrict__ xh) {
    __shared__ float s[1024];
    size_t base = (size_t)blockIdx.x * 1024;
    int t = threadIdx.x;
    int lane = t & 31;
    float v[8];
#pragma unroll
    for (int j = 0; j < 8; j++) v[j] = x[base + t + 128 * j];
    r8(v);  // index bits 7,8,9
#pragma unroll
    for (int j = 0; j < 8; j++) s[t + 128 * j] = v[j];
    __syncthreads();
    float4 p0 = reinterpret_cast<const float4*>(s)[2 * t];
    float4 p1 = reinterpret_cast<const float4*>(s)[2 * t + 1];
    v[0] = p0.x; v[1] = p0.y; v[2] = p0.z; v[3] = p0.w;
    v[4] = p1.x; v[5] = p1.y; v[6] = p1.z; v[7] = p1.w;
    r8(v);  // index bits 0,1,2
#pragma unroll
    for (int m = 1; m <= 8; m <<= 1) {  // index bits 3..6
#pragma unroll
        for (int q = 0; q < 8; q++) {
            float p = __shfl_xor_sync(0xffffffffu, v[q], m);
            v[q] = (lane & m) ? (p - v[q]) : (v[q] + p);
        }
    }
    float4 o0, o1;
    o0.x = tf32r(v[0] * 0.03125f); o0.y = tf32r(v[1] * 0.03125f);
    o0.z = tf32r(v[2] * 0.03125f); o0.w = tf32r(v[3] * 0.03125f);
    o1.x = tf32r(v[4] * 0.03125f); o1.y = tf32r(v[5] * 0.03125f);
    o1.z = tf32r(v[6] * 0.03125f); o1.w = tf32r(v[7] * 0.03125f);
    reinterpret_cast<float4*>(xh + base + 8 * t)[0] = o0;
    reinterpret_cast<float4*>(xh + base + 8 * t)[1] = o1;
}

// ---------------- kernel 2: dequantize W ------------------------------------
__global__ void __launch_bounds__(256) dequant_kernel(const int* __restrict__ codes,
                                                      const float* __restrict__ grid,
                                                      const float* __restrict__ scales,
                                                      float* __restrict__ W) {
    int g = blockIdx.x * 256 + threadIdx.x;      // 0 .. OUT_F*IN_F/2-1
    int o  = g >> 11;                            // row (IN_F/2 = 2048 groups/row)
    int gi = g & 2047;
    int c = codes[g];
    float2 gv = reinterpret_cast<const float2*>(grid)[c];
    float sc = __ldg(scales + o * 4 + (gi >> 9));
    float2 w;
    w.x = tf32r(gv.x * sc);
    w.y = tf32r(gv.y * sc);
    reinterpret_cast<float2*>(W)[g] = w;
}

// ---------------- kernel 3: tf32 GEMM  out = xh @ W^T + bias ----------------
// Round-4 raster: blockIdx.x = N tile, blockIdx.y = M tile.
// Cluster (1,4,1): 4 CTAs share n0 (same B tile). B is loaded by cooperative
// slicing + TMA multicast (each rank loads 64 rows, multicast to all 4):
// per-CTA L2-served tile bytes drop from 48KB to 24KB per k-iter.
#define BM 128
#define BN 256
#define BK 32
#define STAGES 4
#define KITERS (IN_F / BK)
#define A_ST (BM * 128)              // 16 KB per stage
#define B_ST (BN * 128)              // 32 KB per stage
#define B_SLICE (B_ST / CLUSTER_Y)   // 8 KB multicast slice
#define SMA0 1024
#define SMB0 (SMA0 + STAGES * A_ST)
#define SMEM_BYTES (SMB0 + STAGES * B_ST)   // ~193 KB
#define MB0 16                        // full[s] at MB0+16s, empty[s] at +8
#define MB_DONE (MB0 + 16 * STAGES)
#define IDESC 0x8400910u              // F32 acc, tf32 a/b, N=256, M=128

__global__ void __launch_bounds__(256, 1) __cluster_dims__(1, CLUSTER_Y, 1)
gemm_kernel(
    const __grid_constant__ CUtensorMap tma_a,
    const __grid_constant__ CUtensorMap tma_b,
    const float* __restrict__ bias,
    float* __restrict__ out) {
    extern __shared__ char smem[];
    uint32_t sb = smem_u32(smem);
    int tid = threadIdx.x;
    int wid = tid >> 5, lane = tid & 31;
    int n0 = blockIdx.x * BN;
    int m0 = blockIdx.y * BM;

#if HAS_TC
    uint32_t rank = ctarank();
    // ================= tcgen05 path =================
    if (wid == 0) {
        asm volatile("tcgen05.alloc.cta_group::1.sync.aligned.shared::cta.b32 [%0], %1;"
                     :: "r"(sb), "r"(256u) : "memory");
        asm volatile("tcgen05.relinquish_alloc_permit.cta_group::1.sync.aligned;");
    }
    if (tid == 0) {
        for (int s = 0; s < STAGES; s++) {
            mbar_init(sb + MB0 + 16 * s, 1);              // full: 1 local expect-arrive
            mbar_init(sb + MB0 + 16 * s + 8, CLUSTER_Y);  // empty: 4 consumer commits
        }
        mbar_init(sb + MB_DONE, 1);
    }
    __syncthreads();
    // All cluster CTAs' barriers must be live before any multicast targets them.
    asm volatile("barrier.cluster.arrive.aligned;" ::: "memory");
    asm volatile("barrier.cluster.wait.aligned;" ::: "memory");

    uint32_t tmem;
    asm volatile("ld.shared.b32 %0, [%1];" : "=r"(tmem) : "r"(sb));

    if (tid == 0) {
        // ---- TMA producer ----
        int s = 0, ph = 1;  // flipped phase: first STAGES empty-waits pass
        for (int it = 0; it < KITERS; ++it) {
            mbar_wait(sb + MB0 + 16 * s + 8, (uint32_t)ph);
            mbar_expect(sb + MB0 + 16 * s, A_ST + B_ST);
            // local A tile (16 KB)
            tma2d(sb + SMA0 + s * A_ST, &tma_a, it * BK, m0, sb + MB0 + 16 * s);
            // cooperative B slice (8 KB), multicast to all 4 cluster CTAs
            asm volatile(
                "cp.async.bulk.tensor.2d.shared::cluster.global.tile"
                ".mbarrier::complete_tx::bytes.multicast::cluster "
                "[%0], [%1, {%2, %3}], [%4], %5;"
                :: "r"(sb + SMB0 + s * B_ST + rank * B_SLICE), "l"(&tma_b),
                   "r"(it * BK), "r"(n0 + (int)rank * (BN / CLUSTER_Y)),
                   "r"(sb + MB0 + 16 * s), "h"((uint16_t)((1u << CLUSTER_Y) - 1))
                : "memory");
            if (++s == STAGES) { s = 0; ph ^= 1; }
        }
    } else if (tid == 32) {
        // ---- MMA consumer ----
        int s = 0, ph = 0;
        uint32_t acc = 0;
        for (int it = 0; it < KITERS; ++it) {
            mbar_wait(sb + MB0 + 16 * s, (uint32_t)ph);
            // K-major SW128 smem descriptor: layout=2, ver=1, SBO=64, LBO=1
            uint64_t ad = ((uint64_t)2 << 61) | (1ull << 46) | (64ull << 32) | (1ull << 16)
                        | ((uint64_t)((sb + SMA0 + s * A_ST) >> 4) & 0x3FFF);
            uint64_t bd = ((uint64_t)2 << 61) | (1ull << 46) | (64ull << 32) | (1ull << 16)
                        | ((uint64_t)((sb + SMB0 + s * B_ST) >> 4) & 0x3FFF);
#pragma unroll
            for (int kk = 0; kk < 4; kk++) {       // 4 x K=8 tf32 chunks (32B each)
                asm volatile(
                    "{\n\t.reg .pred p;\n\t"
                    "setp.ne.u32 p, %4, 0;\n\t"
                    "tcgen05.mma.cta_group::1.kind::tf32 [%0], %1, %2, %3, {%5, %5, %5, %5}, p;\n\t"
                    "}"
                    :: "r"(tmem), "l"(ad + kk * 2), "l"(bd + kk * 2), "r"(IDESC),
                       "r"(acc), "r"(0u) : "memory");
                acc = 1;
            }
            // release stage s in ALL cluster CTAs when these MMAs complete
            asm volatile(
                "tcgen05.commit.cta_group::1.mbarrier::arrive::one.shared::cluster"
                ".multicast::cluster.b64 [%0], %1;"
                :: "r"(sb + MB0 + 16 * s + 8), "h"((uint16_t)((1u << CLUSTER_Y) - 1))
                : "memory");
            if (++s == STAGES) { s = 0; ph ^= 1; }
        }
        asm volatile("tcgen05.commit.cta_group::1.mbarrier::arrive::one.shared::cluster.b64 [%0];"
                     :: "r"(sb + MB_DONE) : "memory");
    }

    // ---- epilogue: 8 warps; warps 0-3 cols 0-127, warps 4-7 cols 128-255 ----
    mbar_wait(sb + MB_DONE, 0u);
    asm volatile("tcgen05.fence::after_thread_sync;" ::: "memory");

    int m = m0 + (wid & 3) * 32 + lane;
    int cbase = (wid >> 2) * 128;
    float* orow = out + (size_t)m * OUT_F + n0 + cbase;
    const float* brow = bias + n0 + cbase;
#pragma unroll 1
    for (int j = 0; j < 4; ++j) {
        uint32_t r[32];
        asm volatile("tcgen05.ld.sync.aligned.32x32b.x32.b32 "
            "{%0, %1, %2, %3, %4, %5, %6, %7, %8, %9, %10, %11, %12, %13, %14, %15, "
            "%16, %17, %18, %19, %20, %21, %22, %23, %24, %25, %26, %27, %28, %29, %30, %31}, [%32];"
            : "=r"(r[0]), "=r"(r[1]), "=r"(r[2]), "=r"(r[3]),
              "=r"(r[4]), "=r"(r[5]), "=r"(r[6]), "=r"(r[7]),
              "=r"(r[8]), "=r"(r[9]), "=r"(r[10]), "=r"(r[11]),
              "=r"(r[12]), "=r"(r[13]), "=r"(r[14]), "=r"(r[15]),
              "=r"(r[16]), "=r"(r[17]), "=r"(r[18]), "=r"(r[19]),
              "=r"(r[20]), "=r"(r[21]), "=r"(r[22]), "=r"(r[23]),
              "=r"(r[24]), "=r"(r[25]), "=r"(r[26]), "=r"(r[27]),
              "=r"(r[28]), "=r"(r[29]), "=r"(r[30]), "=r"(r[31])
            : "r"(tmem + cbase + j * 32));
        asm volatile("tcgen05.wait::ld.sync.aligned;" ::: "memory");
        float f[32];
#pragma unroll
        for (int c = 0; c < 32; c++) f[c] = __uint_as_float(r[c]) + __ldg(brow + j * 32 + c);
#pragma unroll
        for (int q = 0; q < 8; q++) {
            float4 o; o.x = f[4 * q]; o.y = f[4 * q + 1]; o.z = f[4 * q + 2]; o.w = f[4 * q + 3];
            reinterpret_cast<float4*>(orow + j * 32)[q] = o;
        }
    }
    __syncthreads();
    if (wid == 0) {
        asm volatile("tcgen05.dealloc.cta_group::1.sync.aligned.b32 %0, %1;"
                     :: "r"(tmem), "r"(256u));
    }
    // no CTA exits while peers' multicasts into its smem could be in flight
    asm volatile("barrier.cluster.arrive.aligned;" ::: "memory");
    asm volatile("barrier.cluster.wait.aligned;" ::: "memory");
#else
    // ================= fallback: mma.sync m16n8k8 tf32 =================
    // 8 warps, warp grid 2(M) x 4(N), warp tile 64x64. Unicast TMA pipeline;
    // each CTA loads its full B tile in CLUSTER_Y slices (same tensormap box).
    if (tid == 0) {
        for (int s = 0; s < STAGES; s++) mbar_init(sb + MB0 + 16 * s, 1);  // full only
    }
    __syncthreads();
    if (tid == 0) {
#pragma unroll
        for (int s = 0; s < STAGES; s++) {
            mbar_expect(sb + MB0 + 16 * s, A_ST + B_ST);
            tma2d(sb + SMA0 + s * A_ST, &tma_a, s * BK, m0, sb + MB0 + 16 * s);
            for (int r = 0; r < CLUSTER_Y; r++)
                tma2d(sb + SMB0 + s * B_ST + r * B_SLICE, &tma_b, s * BK,
                      n0 + r * (BN / CLUSTER_Y), sb + MB0 + 16 * s);
        }
    }
    int wm = (wid & 1) * 64;
    int wn = (wid >> 1) * 64;
    float c[4][8][4];
#pragma unroll
    for (int mi = 0; mi < 4; mi++)
#pragma unroll
        for (int ni = 0; ni < 8; ni++)
#pragma unroll
            for (int q = 0; q < 4; q++) c[mi][ni][q] = 0.f;

    int lr = lane >> 2, lc = lane & 3;
#pragma unroll 1
    for (int it = 0; it < KITERS; ++it) {
        int s = it & (STAGES - 1);
        mbar_wait(sb + MB0 + 16 * s, (uint32_t)((it / STAGES) & 1));
        uint32_t sA = sb + SMA0 + s * A_ST;
        uint32_t sB = sb + SMB0 + s * B_ST;
#pragma unroll
        for (int kk = 0; kk < 4; kk++) {
            uint32_t a[4][4];
            uint32_t kc = kk * 8 + lc;
#pragma unroll
            for (int mi = 0; mi < 4; mi++) {
                uint32_t r0 = wm + mi * 16 + lr;
                a[mi][0] = __float_as_uint(lds32(sA + sw128(r0 * 128 + kc * 4)));
                a[mi][1] = __float_as_uint(lds32(sA + sw128((r0 + 8) * 128 + kc * 4)));
                a[mi][2] = __float_as_uint(lds32(sA + sw128(r0 * 128 + (kc + 4) * 4)));
                a[mi][3] = __float_as_uint(lds32(sA + sw128((r0 + 8) * 128 + (kc + 4) * 4)));
            }
            uint32_t b[8][2];
#pragma unroll
            for (int ni = 0; ni < 8; ni++) {
                uint32_t n = wn + ni * 8 + lr;
                b[ni][0] = __float_as_uint(lds32(sB + sw128(n * 128 + kc * 4)));
                b[ni][1] = __float_as_uint(lds32(sB + sw128(n * 128 + (kc + 4) * 4)));
            }
#pragma unroll
            for (int mi = 0; mi < 4; mi++)
#pragma unroll
                for (int ni = 0; ni < 8; ni++) {
                    asm volatile(
                        "mma.sync.aligned.m16n8k8.row.col.f32.tf32.tf32.f32 "
                        "{%0,%1,%2,%3}, {%4,%5,%6,%7}, {%8,%9}, {%0,%1,%2,%3};"
                        : "+f"(c[mi][ni][0]), "+f"(c[mi][ni][1]),
                          "+f"(c[mi][ni][2]), "+f"(c[mi][ni][3])
                        : "r"(a[mi][0]), "r"(a[mi][1]), "r"(a[mi][2]), "r"(a[mi][3]),
                          "r"(b[ni][0]), "r"(b[ni][1]));
                }
        }
        __syncthreads();
        if (tid == 0 && it + STAGES < KITERS) {
            mbar_expect(sb + MB0 + 16 * s, A_ST + B_ST);
            tma2d(sb + SMA0 + s * A_ST, &tma_a, (it + STAGES) * BK, m0, sb + MB0 + 16 * s);
            for (int r = 0; r < CLUSTER_Y; r++)
                tma2d(sb + SMB0 + s * B_ST + r * B_SLICE, &tma_b, (it + STAGES) * BK,
                      n0 + r * (BN / CLUSTER_Y), sb + MB0 + 16 * s);
        }
    }
    // epilogue
#pragma unroll
    for (int mi = 0; mi < 4; mi++) {
        int row = m0 + wm + mi * 16 + lr;
#pragma unroll
        for (int ni = 0; ni < 8; ni++) {
            int col = n0 + wn + ni * 8 + lc * 2;
            float2 v0, v1;
            v0.x = c[mi][ni][0] + __ldg(bias + col);
            v0.y = c[mi][ni][1] + __ldg(bias + col + 1);
            v1.x = c[mi][ni][2] + __ldg(bias + col);
            v1.y = c[mi][ni][3] + __ldg(bias + col + 1);
            *reinterpret_cast<float2*>(out + (size_t)row * OUT_F + col) = v0;
            *reinterpret_cast<float2*>(out + (size_t)(row + 8) * OUT_F + col) = v1;
        }
    }
#endif
}

// ---------------- host launch ------------------------------------------------
extern "C" void kernel_launch(void* const* d_in, const int* in_sizes, int n_in,
                              void* d_out, int out_size) {
    (void)in_sizes; (void)n_in; (void)out_size;
    const float* x      = (const float*)d_in[0];
    const int*   codes  = (const int*)d_in[1];
    const float* grid   = (const float*)d_in[2];
    const float* scales = (const float*)d_in[3];
    const float* bias   = (const float*)d_in[4];
    float* out = (float*)d_out;

    void* xh_ptr = nullptr; void* w_ptr = nullptr;
    cudaGetSymbolAddress(&xh_ptr, g_xh);
    cudaGetSymbolAddress(&w_ptr, g_w);

    typedef CUresult (*EncodeFn)(CUtensorMap*, CUtensorMapDataType, cuuint32_t, void*,
        const cuuint64_t*, const cuuint64_t*, const cuuint32_t*, const cuuint32_t*,
        CUtensorMapInterleave, CUtensorMapSwizzle, CUtensorMapL2promotion,
        CUtensorMapFloatOOBfill);
    void* fp = nullptr;
    cudaDriverEntryPointQueryResult qr;
    cudaGetDriverEntryPoint("cuTensorMapEncodeTiled", &fp, cudaEnableDefault, &qr);
    EncodeFn enc = (EncodeFn)fp;

    CUtensorMap tma_a, tma_b;
    {
        cuuint64_t dims[2]    = {IN_F, TOKENS};
        cuuint64_t strides[1] = {IN_F * 4};
        cuuint32_t box[2]     = {BK, BM};
        cuuint32_t es[2]      = {1, 1};
        enc(&tma_a, CU_TENSOR_MAP_DATA_TYPE_FLOAT32, 2, xh_ptr, dims, strides, box, es,
            CU_TENSOR_MAP_INTERLEAVE_NONE, CU_TENSOR_MAP_SWIZZLE_128B,
            CU_TENSOR_MAP_L2_PROMOTION_L2_128B, CU_TENSOR_MAP_FLOAT_OOB_FILL_NONE);
    }
    {
        cuuint64_t dims[2]    = {IN_F, OUT_F};
        cuuint64_t strides[1] = {IN_F * 4};
        cuuint32_t box[2]     = {BK, BN / CLUSTER_Y};   // 64-row multicast slice
        cuuint32_t es[2]      = {1, 1};
        enc(&tma_b, CU_TENSOR_MAP_DATA_TYPE_FLOAT32, 2, w_ptr, dims, strides, box, es,
            CU_TENSOR_MAP_INTERLEAVE_NONE, CU_TENSOR_MAP_SWIZZLE_128B,
            CU_TENSOR_MAP_L2_PROMOTION_L2_128B, CU_TENSOR_MAP_FLOAT_OOB_FILL_NONE);
    }

    cudaFuncSetAttribute(gemm_kernel, cudaFuncAttributeMaxDynamicSharedMemorySize, SMEM_BYTES);

    fwht_kernel<<<(TOKENS * IN_F) / 1024, 128>>>(x, (float*)xh_ptr);
    dequant_kernel<<<(OUT_F * IN_F / 2) / 256, 256>>>(codes, grid, scales, (float*)w_ptr);
    gemm_kernel<<<dim3(OUT_F / BN, TOKENS / BM), 256, SMEM_BYTES>>>(tma_a, tma_b, bias, out);
}

// round 7
// speedup vs baseline: 1.1782x; 1.1782x over previous
#include <cuda_runtime.h>
#include <cuda.h>
#include <cstdint>

#define TOKENS 8192
#define IN_F   4096
#define OUT_F  4096

#if defined(__CUDA_ARCH_FEAT_SM103_ALL) || defined(__CUDA_ARCH_FEAT_SM100_ALL) || defined(__CUDA_ARCH_FEAT_SM101_ALL)
#define HAS_TC 1
#else
#define HAS_TC 0
#endif

// ---------------- scratch (device globals: no allocations allowed) ----------
__device__ float g_xh[(size_t)TOKENS * IN_F];   // Hadamard-transformed x (tf32-rounded)
__device__ float g_w [(size_t)OUT_F  * IN_F];   // dequantized W (tf32-rounded)

// ---------------- small PTX helpers ----------------------------------------
__device__ __forceinline__ uint32_t smem_u32(const void* p) {
    uint32_t a;
    asm("{ .reg .u64 t; cvta.to.shared.u64 t, %1; cvt.u32.u64 %0, t; }" : "=r"(a) : "l"(p));
    return a;
}
__device__ __forceinline__ float tf32r(float x) {
    uint32_t u; asm("cvt.rna.tf32.f32 %0, %1;" : "=r"(u) : "f"(x));
    return __uint_as_float(u);
}
__device__ __forceinline__ void mbar_init(uint32_t a, uint32_t cnt) {
    asm volatile("mbarrier.init.shared.b64 [%0], %1;" :: "r"(a), "r"(cnt) : "memory");
}
__device__ __forceinline__ void mbar_expect(uint32_t a, uint32_t bytes) {
    asm volatile("mbarrier.arrive.expect_tx.shared.b64 _, [%0], %1;" :: "r"(a), "r"(bytes) : "memory");
}
__device__ __forceinline__ void mbar_wait(uint32_t a, uint32_t parity) {
    asm volatile(
        "{\n\t.reg .pred P;\n\t"
        "WAITLP_%=:\n\t"
        "mbarrier.try_wait.parity.shared::cta.b64 P, [%0], %1, 0x989680;\n\t"
        "@!P bra WAITLP_%=;\n\t"
        "}" :: "r"(a), "r"(parity) : "memory");
}
__device__ __forceinline__ void tma2d(uint32_t dst, const void* map, int cx, int cy, uint32_t bar) {
    asm volatile(
        "cp.async.bulk.tensor.2d.shared::cta.global.tile.mbarrier::complete_tx::bytes "
        "[%0], [%1, {%2, %3}], [%4];"
        :: "r"(dst), "l"(map), "r"(cx), "r"(cy), "r"(bar) : "memory");
}

// ---------------- kernel 1: blockwise FWHT of x (block = 1024) --------------
// Bit coverage (index = 10 bits):
//   phase 1: r8 over j in layout idx = t + 128*j  -> bits {7,8,9}
//   phase 2: r8 over q in layout idx = 8*t + q    -> bits {0,1,2}
//            shfl.bfly m=1,2,4,8 over lane        -> bits {3,4,5,6}
__device__ __forceinline__ void r8(float v[8]) {
    float a;
    a = v[0]; v[0] = a + v[1]; v[1] = a - v[1];
    a = v[2]; v[2] = a + v[3]; v[3] = a - v[3];
    a = v[4]; v[4] = a + v[5]; v[5] = a - v[5];
    a = v[6]; v[6] = a + v[7]; v[7] = a - v[7];
    a = v[0]; v[0] = a + v[2]; v[2] = a - v[2];
    a = v[1]; v[1] = a + v[3]; v[3] = a - v[3];
    a = v[4]; v[4] = a + v[6]; v[6] = a - v[6];
    a = v[5]; v[5] = a + v[7]; v[7] = a - v[7];
    a = v[0]; v[0] = a + v[4]; v[4] = a - v[4];
    a = v[1]; v[1] = a + v[5]; v[5] = a - v[5];
    a = v[2]; v[2] = a + v[6]; v[6] = a - v[6];
    a = v[3]; v[3] = a + v[7]; v[7] = a - v[7];
}

__global__ void __launch_bounds__(128) fwht_kernel(const float* __restrict__ x,
                                                   float* __restrict__ xh) {
    __shared__ float s[1024];
    size_t base = (size_t)blockIdx.x * 1024;
    int t = threadIdx.x;
    int lane = t & 31;
    float v[8];
#pragma unroll
    for (int j = 0; j < 8; j++) v[j] = x[base + t + 128 * j];
    r8(v);  // index bits 7,8,9
#pragma unroll
    for (int j = 0; j < 8; j++) s[t + 128 * j] = v[j];
    __syncthreads();
    float4 p0 = reinterpret_cast<const float4*>(s)[2 * t];
    float4 p1 = reinterpret_cast<const float4*>(s)[2 * t + 1];
    v[0] = p0.x; v[1] = p0.y; v[2] = p0.z; v[3] = p0.w;
    v[4] = p1.x; v[5] = p1.y; v[6] = p1.z; v[7] = p1.w;
    r8(v);  // index bits 0,1,2
#pragma unroll
    for (int m = 1; m <= 8; m <<= 1) {  // index bits 3..6
#pragma unroll
        for (int q = 0; q < 8; q++) {
            float p = __shfl_xor_sync(0xffffffffu, v[q], m);
            v[q] = (lane & m) ? (p - v[q]) : (v[q] + p);
        }
    }
    float4 o0, o1;
    o0.x = tf32r(v[0] * 0.03125f); o0.y = tf32r(v[1] * 0.03125f);
    o0.z = tf32r(v[2] * 0.03125f); o0.w = tf32r(v[3] * 0.03125f);
    o1.x = tf32r(v[4] * 0.03125f); o1.y = tf32r(v[5] * 0.03125f);
    o1.z = tf32r(v[6] * 0.03125f); o1.w = tf32r(v[7] * 0.03125f);
    reinterpret_cast<float4*>(xh + base + 8 * t)[0] = o0;
    reinterpret_cast<float4*>(xh + base + 8 * t)[1] = o1;
}

// ---------------- kernel 2: dequantize W ------------------------------------
__global__ void __launch_bounds__(256) dequant_kernel(const int* __restrict__ codes,
                                                      const float* __restrict__ grid,
                                                      const float* __restrict__ scales,
                                                      float* __restrict__ W) {
    int g = blockIdx.x * 256 + threadIdx.x;      // 0 .. OUT_F*IN_F/2-1
    int o  = g >> 11;                            // row (IN_F/2 = 2048 groups/row)
    int gi = g & 2047;
    int c = codes[g];
    float2 gv = reinterpret_cast<const float2*>(grid)[c];
    float sc = __ldg(scales + o * 4 + (gi >> 9));
    float2 w;
    w.x = tf32r(gv.x * sc);
    w.y = tf32r(gv.y * sc);
    reinterpret_cast<float2*>(W)[g] = w;
}

// ---------------- kernel 3: tf32 GEMM  out = xh @ W^T + bias ----------------
// BM=256 x BN=256 tile, single CTA (no clusters). Two M=128 MMA dispatches per
// K-chunk into two TMEM accumulators (cols 0-255 and 256-511). Round-4 raster:
// blockIdx.x = N tile, blockIdx.y = M tile (consecutive bids share the A tile).
#define BM 256
#define BN 256
#define BK 32
#define STAGES 3
#define KITERS (IN_F / BK)
#define A_ST (BM * 128)              // 32 KB per stage (256 rows x 128B)
#define B_ST (BN * 128)              // 32 KB per stage
#define SMA0 1024
#define SMB0 (SMA0 + STAGES * A_ST)
#define SMEM_BYTES (SMB0 + STAGES * B_ST)   // 197632
#define MB0 16                        // full[s] at MB0+16s, empty[s] at +8
#define MB_DONE (MB0 + 16 * STAGES)
#define IDESC 0x8400910u              // F32 acc, tf32 a/b, N=256, M=128

__global__ void __launch_bounds__(256, 1) gemm_kernel(
    const __grid_constant__ CUtensorMap tma_a,
    const __grid_constant__ CUtensorMap tma_b,
    const float* __restrict__ bias,
    float* __restrict__ out) {
    extern __shared__ char smem[];
    uint32_t sb = smem_u32(smem);
    int tid = threadIdx.x;
    int wid = tid >> 5, lane = tid & 31;
    int n0 = blockIdx.x * BN;
    int m0 = blockIdx.y * BM;

#if HAS_TC
    // ================= tcgen05 path =================
    if (wid == 0) {
        asm volatile("tcgen05.alloc.cta_group::1.sync.aligned.shared::cta.b32 [%0], %1;"
                     :: "r"(sb), "r"(512u) : "memory");
        asm volatile("tcgen05.relinquish_alloc_permit.cta_group::1.sync.aligned;");
    }
    if (tid == 0) {
        for (int s = 0; s < STAGES; s++) {
            mbar_init(sb + MB0 + 16 * s, 1);       // full
            mbar_init(sb + MB0 + 16 * s + 8, 1);   // empty
        }
        mbar_init(sb + MB_DONE, 1);
    }
    __syncthreads();
    uint32_t tmem;
    asm volatile("ld.shared.b32 %0, [%1];" : "=r"(tmem) : "r"(sb));

    if (tid == 0) {
        // ---- TMA producer ----
        int s = 0, ph = 1;  // flipped phase: first STAGES empty-waits pass
        for (int it = 0; it < KITERS; ++it) {
            mbar_wait(sb + MB0 + 16 * s + 8, (uint32_t)ph);
            mbar_expect(sb + MB0 + 16 * s, A_ST + B_ST);
            tma2d(sb + SMA0 + s * A_ST, &tma_a, it * BK, m0, sb + MB0 + 16 * s);
            tma2d(sb + SMB0 + s * B_ST, &tma_b, it * BK, n0, sb + MB0 + 16 * s);
            if (++s == STAGES) { s = 0; ph ^= 1; }
        }
    } else if (tid == 32) {
        // ---- MMA consumer: 2 M-halves x 4 K-chunks per stage ----
        int s = 0, ph = 0;
        uint32_t acc = 0;
        for (int it = 0; it < KITERS; ++it) {
            mbar_wait(sb + MB0 + 16 * s, (uint32_t)ph);
            // K-major SW128 smem descriptor: layout=2, ver=1, SBO=64, LBO=1
            uint64_t ad0 = ((uint64_t)2 << 61) | (1ull << 46) | (64ull << 32) | (1ull << 16)
                         | ((uint64_t)((sb + SMA0 + s * A_ST) >> 4) & 0x3FFF);
            uint64_t ad1 = ad0 + 1024;   // +16 KB: A rows 128..255
            uint64_t bd  = ((uint64_t)2 << 61) | (1ull << 46) | (64ull << 32) | (1ull << 16)
                         | ((uint64_t)((sb + SMB0 + s * B_ST) >> 4) & 0x3FFF);
#pragma unroll
            for (int kk = 0; kk < 4; kk++) {       // 4 x K=8 tf32 chunks (32B each)
                asm volatile(
                    "{\n\t.reg .pred p;\n\t"
                    "setp.ne.u32 p, %4, 0;\n\t"
                    "tcgen05.mma.cta_group::1.kind::tf32 [%0], %1, %2, %3, {%5, %5, %5, %5}, p;\n\t"
                    "}"
                    :: "r"(tmem), "l"(ad0 + kk * 2), "l"(bd + kk * 2), "r"(IDESC),
                       "r"(acc), "r"(0u) : "memory");
                asm volatile(
                    "{\n\t.reg .pred p;\n\t"
                    "setp.ne.u32 p, %4, 0;\n\t"
                    "tcgen05.mma.cta_group::1.kind::tf32 [%0], %1, %2, %3, {%5, %5, %5, %5}, p;\n\t"
                    "}"
                    :: "r"(tmem + 256), "l"(ad1 + kk * 2), "l"(bd + kk * 2), "r"(IDESC),
                       "r"(acc), "r"(0u) : "memory");
                acc = 1;
            }
            asm volatile("tcgen05.commit.cta_group::1.mbarrier::arrive::one.shared::cluster.b64 [%0];"
                         :: "r"(sb + MB0 + 16 * s + 8) : "memory");
            if (++s == STAGES) { s = 0; ph ^= 1; }
        }
        asm volatile("tcgen05.commit.cta_group::1.mbarrier::arrive::one.shared::cluster.b64 [%0];"
                     :: "r"(sb + MB_DONE) : "memory");
    }

    // ---- epilogue: warps 0-3 -> rows 0-127 (tmem cols 0-255),
    //                warps 4-7 -> rows 128-255 (tmem cols 256-511) ----
    mbar_wait(sb + MB_DONE, 0u);
    asm volatile("tcgen05.fence::after_thread_sync;" ::: "memory");

    int h = wid >> 2;
    int m = m0 + h * 128 + (wid & 3) * 32 + lane;
    float* orow = out + (size_t)m * OUT_F + n0;
    const float* brow = bias + n0;
#pragma unroll 1
    for (int j = 0; j < 8; ++j) {
        uint32_t r[32];
        asm volatile("tcgen05.ld.sync.aligned.32x32b.x32.b32 "
            "{%0, %1, %2, %3, %4, %5, %6, %7, %8, %9, %10, %11, %12, %13, %14, %15, "
            "%16, %17, %18, %19, %20, %21, %22, %23, %24, %25, %26, %27, %28, %29, %30, %31}, [%32];"
            : "=r"(r[0]), "=r"(r[1]), "=r"(r[2]), "=r"(r[3]),
              "=r"(r[4]), "=r"(r[5]), "=r"(r[6]), "=r"(r[7]),
              "=r"(r[8]), "=r"(r[9]), "=r"(r[10]), "=r"(r[11]),
              "=r"(r[12]), "=r"(r[13]), "=r"(r[14]), "=r"(r[15]),
              "=r"(r[16]), "=r"(r[17]), "=r"(r[18]), "=r"(r[19]),
              "=r"(r[20]), "=r"(r[21]), "=r"(r[22]), "=r"(r[23]),
              "=r"(r[24]), "=r"(r[25]), "=r"(r[26]), "=r"(r[27]),
              "=r"(r[28]), "=r"(r[29]), "=r"(r[30]), "=r"(r[31])
            : "r"(tmem + h * 256 + j * 32));
        asm volatile("tcgen05.wait::ld.sync.aligned;" ::: "memory");
        float f[32];
#pragma unroll
        for (int c = 0; c < 32; c++) f[c] = __uint_as_float(r[c]) + __ldg(brow + j * 32 + c);
#pragma unroll
        for (int q = 0; q < 8; q++) {
            float4 o; o.x = f[4 * q]; o.y = f[4 * q + 1]; o.z = f[4 * q + 2]; o.w = f[4 * q + 3];
            reinterpret_cast<float4*>(orow + j * 32)[q] = o;
        }
    }
    __syncthreads();
    if (wid == 0) {
        asm volatile("tcgen05.dealloc.cta_group::1.sync.aligned.b32 %0, %1;"
                     :: "r"(tmem), "r"(512u));
    }
#else
    // ===== never-run fallback (family-generic PTX pass must compile) =====
    // The sm_103a cubin always wins at load time; this exists for compilation
    // of the compute_103 pass and is correct (but slow) if ever executed.
    for (int oi = tid; oi < BM * BN; oi += 256) {
        int r = m0 + oi / BN;
        int c = n0 + oi % BN;
        float acc = __ldg(bias + c);
        const float* ar = g_xh + (size_t)r * IN_F;
        const float* wr = g_w + (size_t)c * IN_F;
        for (int k = 0; k < IN_F; k++) acc += ar[k] * wr[k];
        out[(size_t)r * OUT_F + c] = acc;
    }
#endif
}

// ---------------- host launch ------------------------------------------------
extern "C" void kernel_launch(void* const* d_in, const int* in_sizes, int n_in,
                              void* d_out, int out_size) {
    (void)in_sizes; (void)n_in; (void)out_size;
    const float* x      = (const float*)d_in[0];
    const int*   codes  = (const int*)d_in[1];
    const float* grid   = (const float*)d_in[2];
    const float* scales = (const float*)d_in[3];
    const float* bias   = (const float*)d_in[4];
    float* out = (float*)d_out;

    void* xh_ptr = nullptr; void* w_ptr = nullptr;
    cudaGetSymbolAddress(&xh_ptr, g_xh);
    cudaGetSymbolAddress(&w_ptr, g_w);

    typedef CUresult (*EncodeFn)(CUtensorMap*, CUtensorMapDataType, cuuint32_t, void*,
        const cuuint64_t*, const cuuint64_t*, const cuuint32_t*, const cuuint32_t*,
        CUtensorMapInterleave, CUtensorMapSwizzle, CUtensorMapL2promotion,
        CUtensorMapFloatOOBfill);
    void* fp = nullptr;
    cudaDriverEntryPointQueryResult qr;
    cudaGetDriverEntryPoint("cuTensorMapEncodeTiled", &fp, cudaEnableDefault, &qr);
    EncodeFn enc = (EncodeFn)fp;

    CUtensorMap tma_a, tma_b;
    {
        cuuint64_t dims[2]    = {IN_F, TOKENS};
        cuuint64_t strides[1] = {IN_F * 4};
        cuuint32_t box[2]     = {BK, BM};      // 32 x 256
        cuuint32_t es[2]      = {1, 1};
        enc(&tma_a, CU_TENSOR_MAP_DATA_TYPE_FLOAT32, 2, xh_ptr, dims, strides, box, es,
            CU_TENSOR_MAP_INTERLEAVE_NONE, CU_TENSOR_MAP_SWIZZLE_128B,
            CU_TENSOR_MAP_L2_PROMOTION_L2_128B, CU_TENSOR_MAP_FLOAT_OOB_FILL_NONE);
    }
    {
        cuuint64_t dims[2]    = {IN_F, OUT_F};
        cuuint64_t strides[1] = {IN_F * 4};
        cuuint32_t box[2]     = {BK, BN};      // 32 x 256
        cuuint32_t es[2]      = {1, 1};
        enc(&tma_b, CU_TENSOR_MAP_DATA_TYPE_FLOAT32, 2, w_ptr, dims, strides, box, es,
            CU_TENSOR_MAP_INTERLEAVE_NONE, CU_TENSOR_MAP_SWIZZLE_128B,
            CU_TENSOR_MAP_L2_PROMOTION_L2_128B, CU_TENSOR_MAP_FLOAT_OOB_FILL_NONE);
    }

    cudaFuncSetAttribute(gemm_kernel, cudaFuncAttributeMaxDynamicSharedMemorySize, SMEM_BYTES);

    fwht_kernel<<<(TOKENS * IN_F) / 1024, 128>>>(x, (float*)xh_ptr);
    dequant_kernel<<<(OUT_F * IN_F / 2) / 256, 256>>>(codes, grid, scales, (float*)w_ptr);
    gemm_kernel<<<dim3(OUT_F / BN, TOKENS / BM), 256, SMEM_BYTES>>>(tma_a, tma_b, bias, out);
}

// round 8
// speedup vs baseline: 1.8465x; 1.5673x over previous
#include <cuda_runtime.h>
#include <cuda.h>
#include <cuda_fp16.h>
#include <cstdint>

#define TOKENS 8192
#define IN_F   4096
#define OUT_F  4096

#if defined(__CUDA_ARCH_FEAT_SM103_ALL) || defined(__CUDA_ARCH_FEAT_SM100_ALL) || defined(__CUDA_ARCH_FEAT_SM101_ALL)
#define HAS_TC 1
#else
#define HAS_TC 0
#endif

// ---------------- scratch (device globals: no allocations allowed) ----------
__device__ __half g_xh[(size_t)TOKENS * IN_F];  // Hadamard-transformed x (fp16)
__device__ __half g_w [(size_t)OUT_F  * IN_F];  // dequantized W (fp16)

// ---------------- small PTX helpers ----------------------------------------
__device__ __forceinline__ uint32_t smem_u32(const void* p) {
    uint32_t a;
    asm("{ .reg .u64 t; cvta.to.shared.u64 t, %1; cvt.u32.u64 %0, t; }" : "=r"(a) : "l"(p));
    return a;
}
__device__ __forceinline__ void mbar_init(uint32_t a, uint32_t cnt) {
    asm volatile("mbarrier.init.shared.b64 [%0], %1;" :: "r"(a), "r"(cnt) : "memory");
}
__device__ __forceinline__ void mbar_expect(uint32_t a, uint32_t bytes) {
    asm volatile("mbarrier.arrive.expect_tx.shared.b64 _, [%0], %1;" :: "r"(a), "r"(bytes) : "memory");
}
__device__ __forceinline__ void mbar_wait(uint32_t a, uint32_t parity) {
    asm volatile(
        "{\n\t.reg .pred P;\n\t"
        "WAITLP_%=:\n\t"
        "mbarrier.try_wait.parity.shared::cta.b64 P, [%0], %1, 0x989680;\n\t"
        "@!P bra WAITLP_%=;\n\t"
        "}" :: "r"(a), "r"(parity) : "memory");
}
__device__ __forceinline__ void tma2d(uint32_t dst, const void* map, int cx, int cy, uint32_t bar) {
    asm volatile(
        "cp.async.bulk.tensor.2d.shared::cta.global.tile.mbarrier::complete_tx::bytes "
        "[%0], [%1, {%2, %3}], [%4];"
        :: "r"(dst), "l"(map), "r"(cx), "r"(cy), "r"(bar) : "memory");
}

// ---------------- kernel 1: blockwise FWHT of x (block = 1024) --------------
// Bit coverage (index = 10 bits):
//   phase 1: r8 over j in layout idx = t + 128*j  -> bits {7,8,9}
//   phase 2: r8 over q in layout idx = 8*t + q    -> bits {0,1,2}
//            shfl.bfly m=1,2,4,8 over lane        -> bits {3,4,5,6}
__device__ __forceinline__ void r8(float v[8]) {
    float a;
    a = v[0]; v[0] = a + v[1]; v[1] = a - v[1];
    a = v[2]; v[2] = a + v[3]; v[3] = a - v[3];
    a = v[4]; v[4] = a + v[5]; v[5] = a - v[5];
    a = v[6]; v[6] = a + v[7]; v[7] = a - v[7];
    a = v[0]; v[0] = a + v[2]; v[2] = a - v[2];
    a = v[1]; v[1] = a + v[3]; v[3] = a - v[3];
    a = v[4]; v[4] = a + v[6]; v[6] = a - v[6];
    a = v[5]; v[5] = a + v[7]; v[7] = a - v[7];
    a = v[0]; v[0] = a + v[4]; v[4] = a - v[4];
    a = v[1]; v[1] = a + v[5]; v[5] = a - v[5];
    a = v[2]; v[2] = a + v[6]; v[6] = a - v[6];
    a = v[3]; v[3] = a + v[7]; v[7] = a - v[7];
}

__global__ void __launch_bounds__(128) fwht_kernel(const float* __restrict__ x,
                                                   __half* __restrict__ xh) {
    __shared__ float s[1024];
    size_t base = (size_t)blockIdx.x * 1024;
    int t = threadIdx.x;
    int lane = t & 31;
    float v[8];
#pragma unroll
    for (int j = 0; j < 8; j++) v[j] = x[base + t + 128 * j];
    r8(v);  // index bits 7,8,9
#pragma unroll
    for (int j = 0; j < 8; j++) s[t + 128 * j] = v[j];
    __syncthreads();
    float4 p0 = reinterpret_cast<const float4*>(s)[2 * t];
    float4 p1 = reinterpret_cast<const float4*>(s)[2 * t + 1];
    v[0] = p0.x; v[1] = p0.y; v[2] = p0.z; v[3] = p0.w;
    v[4] = p1.x; v[5] = p1.y; v[6] = p1.z; v[7] = p1.w;
    r8(v);  // index bits 0,1,2
#pragma unroll
    for (int m = 1; m <= 8; m <<= 1) {  // index bits 3..6
#pragma unroll
        for (int q = 0; q < 8; q++) {
            float p = __shfl_xor_sync(0xffffffffu, v[q], m);
            v[q] = (lane & m) ? (p - v[q]) : (v[q] + p);
        }
    }
    __half2 h[4];
#pragma unroll
    for (int q = 0; q < 4; q++)
        h[q] = __floats2half2_rn(v[2 * q] * 0.03125f, v[2 * q + 1] * 0.03125f);
    *reinterpret_cast<uint4*>(xh + base + 8 * t) = *reinterpret_cast<uint4*>(h);
}

// ---------------- kernel 2: dequantize W (fp16 out) --------------------------
__global__ void __launch_bounds__(256) dequant_kernel(const int* __restrict__ codes,
                                                      const float* __restrict__ grid,
                                                      const float* __restrict__ scales,
                                                      __half2* __restrict__ W) {
    int g = blockIdx.x * 256 + threadIdx.x;      // 0 .. OUT_F*IN_F/2-1
    int o  = g >> 11;                            // row (IN_F/2 = 2048 groups/row)
    int gi = g & 2047;
    int c = codes[g];
    float2 gv = reinterpret_cast<const float2*>(grid)[c];
    float sc = __ldg(scales + o * 4 + (gi >> 9));
    W[g] = __floats2half2_rn(gv.x * sc, gv.y * sc);
}

// ---------------- kernel 3: fp16 GEMM  out = xh @ W^T + bias ----------------
// BM=256 x BN=256 tile, BK=64 fp16 (128B rows, SW128). Two M=128 MMA
// dispatches per K-chunk into TMEM cols 0-255 / 256-511. Round-4 raster.
#define BM 256
#define BN 256
#define BK 64
#define STAGES 3
#define KITERS (IN_F / BK)            // 64
#define A_ST (BM * 128)               // 32 KB per stage (256 rows x 128B)
#define B_ST (BN * 128)               // 32 KB per stage
#define SMA0 1024
#define SMB0 (SMA0 + STAGES * A_ST)
#define SMEM_BYTES (SMB0 + STAGES * B_ST)   // 197632
#define MB0 16                        // full[s] at MB0+16s, empty[s] at +8
#define MB_DONE (MB0 + 16 * STAGES)
#define IDESC 0x8400010u              // F32 acc, f16 a/b, N=256, M=128

__global__ void __launch_bounds__(256, 1) gemm_kernel(
    const __grid_constant__ CUtensorMap tma_a,
    const __grid_constant__ CUtensorMap tma_b,
    const float* __restrict__ bias,
    float* __restrict__ out) {
    extern __shared__ char smem[];
    uint32_t sb = smem_u32(smem);
    int tid = threadIdx.x;
    int wid = tid >> 5, lane = tid & 31;
    int n0 = blockIdx.x * BN;
    int m0 = blockIdx.y * BM;

#if HAS_TC
    // ================= tcgen05 path =================
    if (wid == 0) {
        asm volatile("tcgen05.alloc.cta_group::1.sync.aligned.shared::cta.b32 [%0], %1;"
                     :: "r"(sb), "r"(512u) : "memory");
        asm volatile("tcgen05.relinquish_alloc_permit.cta_group::1.sync.aligned;");
    }
    if (tid == 0) {
        for (int s = 0; s < STAGES; s++) {
            mbar_init(sb + MB0 + 16 * s, 1);       // full
            mbar_init(sb + MB0 + 16 * s + 8, 1);   // empty
        }
        mbar_init(sb + MB_DONE, 1);
    }
    __syncthreads();
    uint32_t tmem;
    asm volatile("ld.shared.b32 %0, [%1];" : "=r"(tmem) : "r"(sb));

    if (tid == 0) {
        // ---- TMA producer ----
        int s = 0, ph = 1;  // flipped phase: first STAGES empty-waits pass
        for (int it = 0; it < KITERS; ++it) {
            mbar_wait(sb + MB0 + 16 * s + 8, (uint32_t)ph);
            mbar_expect(sb + MB0 + 16 * s, A_ST + B_ST);
            tma2d(sb + SMA0 + s * A_ST, &tma_a, it * BK, m0, sb + MB0 + 16 * s);
            tma2d(sb + SMB0 + s * B_ST, &tma_b, it * BK, n0, sb + MB0 + 16 * s);
            if (++s == STAGES) { s = 0; ph ^= 1; }
        }
    } else if (tid == 32) {
        // ---- MMA consumer: 2 M-halves x 4 K=16 chunks per stage ----
        int s = 0, ph = 0;
        uint32_t acc = 0;
        for (int it = 0; it < KITERS; ++it) {
            mbar_wait(sb + MB0 + 16 * s, (uint32_t)ph);
            // K-major SW128 smem descriptor: layout=2, ver=1, SBO=64, LBO=1
            uint64_t ad0 = ((uint64_t)2 << 61) | (1ull << 46) | (64ull << 32) | (1ull << 16)
                         | ((uint64_t)((sb + SMA0 + s * A_ST) >> 4) & 0x3FFF);
            uint64_t ad1 = ad0 + 1024;   // +16 KB: A rows 128..255
            uint64_t bd  = ((uint64_t)2 << 61) | (1ull << 46) | (64ull << 32) | (1ull << 16)
                         | ((uint64_t)((sb + SMB0 + s * B_ST) >> 4) & 0x3FFF);
#pragma unroll
            for (int kk = 0; kk < 4; kk++) {       // 4 x K=16 f16 chunks (32B each)
                asm volatile(
                    "{\n\t.reg .pred p;\n\t"
                    "setp.ne.u32 p, %4, 0;\n\t"
                    "tcgen05.mma.cta_group::1.kind::f16 [%0], %1, %2, %3, {%5, %5, %5, %5}, p;\n\t"
                    "}"
                    :: "r"(tmem), "l"(ad0 + kk * 2), "l"(bd + kk * 2), "r"(IDESC),
                       "r"(acc), "r"(0u) : "memory");
                asm volatile(
                    "{\n\t.reg .pred p;\n\t"
                    "setp.ne.u32 p, %4, 0;\n\t"
                    "tcgen05.mma.cta_group::1.kind::f16 [%0], %1, %2, %3, {%5, %5, %5, %5}, p;\n\t"
                    "}"
                    :: "r"(tmem + 256), "l"(ad1 + kk * 2), "l"(bd + kk * 2), "r"(IDESC),
                       "r"(acc), "r"(0u) : "memory");
                acc = 1;
            }
            asm volatile("tcgen05.commit.cta_group::1.mbarrier::arrive::one.shared::cluster.b64 [%0];"
                         :: "r"(sb + MB0 + 16 * s + 8) : "memory");
            if (++s == STAGES) { s = 0; ph ^= 1; }
        }
        asm volatile("tcgen05.commit.cta_group::1.mbarrier::arrive::one.shared::cluster.b64 [%0];"
                     :: "r"(sb + MB_DONE) : "memory");
    }

    // ---- epilogue: warps 0-3 -> rows 0-127 (tmem cols 0-255),
    //                warps 4-7 -> rows 128-255 (tmem cols 256-511) ----
    mbar_wait(sb + MB_DONE, 0u);
    asm volatile("tcgen05.fence::after_thread_sync;" ::: "memory");

    int h = wid >> 2;
    int m = m0 + h * 128 + (wid & 3) * 32 + lane;
    float* orow = out + (size_t)m * OUT_F + n0;
    const float* brow = bias + n0;
#pragma unroll 1
    for (int j = 0; j < 8; ++j) {
        uint32_t r[32];
        asm volatile("tcgen05.ld.sync.aligned.32x32b.x32.b32 "
            "{%0, %1, %2, %3, %4, %5, %6, %7, %8, %9, %10, %11, %12, %13, %14, %15, "
            "%16, %17, %18, %19, %20, %21, %22, %23, %24, %25, %26, %27, %28, %29, %30, %31}, [%32];"
            : "=r"(r[0]), "=r"(r[1]), "=r"(r[2]), "=r"(r[3]),
              "=r"(r[4]), "=r"(r[5]), "=r"(r[6]), "=r"(r[7]),
              "=r"(r[8]), "=r"(r[9]), "=r"(r[10]), "=r"(r[11]),
              "=r"(r[12]), "=r"(r[13]), "=r"(r[14]), "=r"(r[15]),
              "=r"(r[16]), "=r"(r[17]), "=r"(r[18]), "=r"(r[19]),
              "=r"(r[20]), "=r"(r[21]), "=r"(r[22]), "=r"(r[23]),
              "=r"(r[24]), "=r"(r[25]), "=r"(r[26]), "=r"(r[27]),
              "=r"(r[28]), "=r"(r[29]), "=r"(r[30]), "=r"(r[31])
            : "r"(tmem + h * 256 + j * 32));
        asm volatile("tcgen05.wait::ld.sync.aligned;" ::: "memory");
        float f[32];
#pragma unroll
        for (int c = 0; c < 32; c++) f[c] = __uint_as_float(r[c]) + __ldg(brow + j * 32 + c);
#pragma unroll
        for (int q = 0; q < 8; q++) {
            float4 o; o.x = f[4 * q]; o.y = f[4 * q + 1]; o.z = f[4 * q + 2]; o.w = f[4 * q + 3];
            reinterpret_cast<float4*>(orow + j * 32)[q] = o;
        }
    }
    __syncthreads();
    if (wid == 0) {
        asm volatile("tcgen05.dealloc.cta_group::1.sync.aligned.b32 %0, %1;"
                     :: "r"(tmem), "r"(512u));
    }
#else
    // ===== never-run fallback (family-generic PTX pass must compile) =====
    for (int oi = tid; oi < BM * BN; oi += 256) {
        int r = m0 + oi / BN;
        int c = n0 + oi % BN;
        float acc = __ldg(bias + c);
        const __half* ar = g_xh + (size_t)r * IN_F;
        const __half* wr = g_w + (size_t)c * IN_F;
        for (int k = 0; k < IN_F; k++) acc += __half2float(ar[k]) * __half2float(wr[k]);
        out[(size_t)r * OUT_F + c] = acc;
    }
#endif
}

// ---------------- host launch ------------------------------------------------
extern "C" void kernel_launch(void* const* d_in, const int* in_sizes, int n_in,
                              void* d_out, int out_size) {
    (void)in_sizes; (void)n_in; (void)out_size;
    const float* x      = (const float*)d_in[0];
    const int*   codes  = (const int*)d_in[1];
    const float* grid   = (const float*)d_in[2];
    const float* scales = (const float*)d_in[3];
    const float* bias   = (const float*)d_in[4];
    float* out = (float*)d_out;

    void* xh_ptr = nullptr; void* w_ptr = nullptr;
    cudaGetSymbolAddress(&xh_ptr, g_xh);
    cudaGetSymbolAddress(&w_ptr, g_w);

    typedef CUresult (*EncodeFn)(CUtensorMap*, CUtensorMapDataType, cuuint32_t, void*,
        const cuuint64_t*, const cuuint64_t*, const cuuint32_t*, const cuuint32_t*,
        CUtensorMapInterleave, CUtensorMapSwizzle, CUtensorMapL2promotion,
        CUtensorMapFloatOOBfill);
    void* fp = nullptr;
    cudaDriverEntryPointQueryResult qr;
    cudaGetDriverEntryPoint("cuTensorMapEncodeTiled", &fp, cudaEnableDefault, &qr);
    EncodeFn enc = (EncodeFn)fp;

    CUtensorMap tma_a, tma_b;
    {
        cuuint64_t dims[2]    = {IN_F, TOKENS};
        cuuint64_t strides[1] = {IN_F * 2};    // fp16
        cuuint32_t box[2]     = {BK, BM};      // 64 x 256 (128B rows)
        cuuint32_t es[2]      = {1, 1};
        enc(&tma_a, CU_TENSOR_MAP_DATA_TYPE_FLOAT16, 2, xh_ptr, dims, strides, box, es,
            CU_TENSOR_MAP_INTERLEAVE_NONE, CU_TENSOR_MAP_SWIZZLE_128B,
            CU_TENSOR_MAP_L2_PROMOTION_L2_128B, CU_TENSOR_MAP_FLOAT_OOB_FILL_NONE);
    }
    {
        cuuint64_t dims[2]    = {IN_F, OUT_F};
        cuuint64_t strides[1] = {IN_F * 2};    // fp16
        cuuint32_t box[2]     = {BK, BN};      // 64 x 256
        cuuint32_t es[2]      = {1, 1};
        enc(&tma_b, CU_TENSOR_MAP_DATA_TYPE_FLOAT16, 2, w_ptr, dims, strides, box, es,
            CU_TENSOR_MAP_INTERLEAVE_NONE, CU_TENSOR_MAP_SWIZZLE_128B,
            CU_TENSOR_MAP_L2_PROMOTION_L2_128B, CU_TENSOR_MAP_FLOAT_OOB_FILL_NONE);
    }

    cudaFuncSetAttribute(gemm_kernel, cudaFuncAttributeMaxDynamicSharedMemorySize, SMEM_BYTES);

    fwht_kernel<<<(TOKENS * IN_F) / 1024, 128>>>(x, (__half*)xh_ptr);
    dequant_kernel<<<(OUT_F * IN_F / 2) / 256, 256>>>(codes, grid, scales, (__half2*)w_ptr);
    gemm_kernel<<<dim3(OUT_F / BN, TOKENS / BM), 256, SMEM_BYTES>>>(tma_a, tma_b, bias, out);
}